// round 16
// baseline (speedup 1.0000x reference)
#include <cuda_runtime.h>
#include <cuda_bf16.h>
#include <cuda_fp16.h>
#include <cstdint>
#include <math.h>

// ---------------------------------------------------------------------------
// MultiLevelSimCLR: symmetric tiles, two independent 4-warp groups per CTA
// (phase-offset tiles), f16x2 exp epilogue, diag masking + pos harvesting.
// ---------------------------------------------------------------------------

#define B_INS   8192
#define N_INS   16384
#define DDIM    128
#define NPROW   131072
#define L2E10   14.4269504088896340f
#define NI_CTAS 688

// ---- static device scratch ----
__device__ __align__(16) uint32_t g_I[N_INS * 64];
__device__ __align__(16) uint32_t g_P[NPROW * 64];
__device__ float g_part[128 * 128 * 128];                // [bi][bj][m]  8.4 MB
__device__ float g_pp[256 * 16 * 128];                   // [b][i*4+j][m] 2.1 MB
__device__ float g_posI[N_INS];
__device__ float g_posP[NPROW];
__device__ float g_fin1[512];
__device__ float g_fin2[1024];
__device__ int   g_cnt2[1024];
__device__ int   g_done;

__device__ __forceinline__ __half2 h2ex2(__half2 x) {
    uint32_t xi = *(uint32_t*)&x, yi;
    asm("ex2.approx.f16x2 %0, %1;" : "=r"(yi) : "r"(xi));
    return *(__half2*)&yi;
}
__device__ __forceinline__ uint32_t smem_u32(const void* p) {
    uint32_t a;
    asm("{ .reg .u64 t; cvta.to.shared.u64 t, %1; cvt.u32.u64 %0, t; }" : "=r"(a) : "l"(p));
    return a;
}
__device__ __forceinline__ void mma16816(float* c, const uint32_t* a, uint32_t b0, uint32_t b1) {
    asm volatile(
        "mma.sync.aligned.m16n8k16.row.col.f32.bf16.bf16.f32 "
        "{%0,%1,%2,%3}, {%4,%5,%6,%7}, {%8,%9}, {%0,%1,%2,%3};"
        : "+f"(c[0]), "+f"(c[1]), "+f"(c[2]), "+f"(c[3])
        : "r"(a[0]), "r"(a[1]), "r"(a[2]), "r"(a[3]), "r"(b0), "r"(b1));
}
__device__ __forceinline__ void ldsm_x4(uint32_t* r, uint32_t addr) {
    asm volatile("ldmatrix.sync.aligned.m8n8.x4.shared.b16 {%0,%1,%2,%3}, [%4];"
        : "=r"(r[0]), "=r"(r[1]), "=r"(r[2]), "=r"(r[3]) : "r"(addr));
}
#define CP_ASYNC16(dst, src) asm volatile("cp.async.cg.shared.global [%0], [%1], 16;" :: "r"(dst), "l"(src))
#define CP_COMMIT()  asm volatile("cp.async.commit_group;" ::: "memory")
#define CP_WAIT0()   asm volatile("cp.async.wait_group 0;" ::: "memory")
#define BAR_G(id)    asm volatile("bar.sync %0, 128;" :: "r"(id) : "memory")

// SMEM: A @0 (32KB), Bgrp0 @32768, Bgrp1 @65536, red[2 groups] @98304 (2x2KB)
#define SM_A    0u
#define SM_B0   32768u
#define SM_RED  98304
#define SM_DYN  (98304 + 4096)

// 256-thread tile copy (prologue A)
__device__ __forceinline__ void cpa_tile256(uint32_t dst, const char* __restrict__ src) {
    int tid = threadIdx.x;
#pragma unroll
    for (int i = 0; i < 8; i++) {
        int c = tid + i * 256;
        int r = c >> 4, cc = c & 15;
        uint32_t d = dst + r * 256 + (((uint32_t)(cc ^ (r & 7))) << 4);
        CP_ASYNC16(d, src + r * 256 + cc * 16);
    }
}
// 128-thread (group-local) tile copy
__device__ __forceinline__ void cpa_tile128(uint32_t dst, const char* __restrict__ src, int gtid) {
#pragma unroll
    for (int i = 0; i < 16; i++) {
        int c = gtid + i * 128;
        int r = c >> 4, cc = c & 15;
        uint32_t d = dst + r * 256 + (((uint32_t)(cc ^ (r & 7))) << 4);
        CP_ASYNC16(d, src + r * 256 + cc * 16);
    }
}

// ---------------------------------------------------------------------------
// Fused prep: blocks 0..511 instance, 512..2559 patch.
// ---------------------------------------------------------------------------
__global__ void prep_all(const float* __restrict__ v1, const float* __restrict__ v2,
                         const float* __restrict__ v1p, const float* __restrict__ v2p) {
    __shared__ float sb[2][32][129];
    int tid = threadIdx.x, lane = tid & 31, wid = tid >> 5;

    if (blockIdx.x < 512) {
        int gw = (blockIdx.x * 256 + tid) >> 5;
        for (int r = gw; r < N_INS; r += 4096) {
            const float* src = (r < B_INS) ? v1 + (size_t)r * DDIM : v2 + (size_t)(r - B_INS) * DDIM;
            float4 x = ((const float4*)src)[lane];
            float ss = x.x * x.x + x.y * x.y + x.z * x.z + x.w * x.w;
#pragma unroll
            for (int o = 16; o; o >>= 1) ss += __shfl_xor_sync(~0u, ss, o);
            float ri = 1.0f / fmaxf(sqrtf(ss), 1e-12f);
            __nv_bfloat162 p0 = __floats2bfloat162_rn(x.x * ri, x.y * ri);
            __nv_bfloat162 p1 = __floats2bfloat162_rn(x.z * ri, x.w * ri);
            ((uint2*)g_I)[(size_t)r * 32 + lane] = make_uint2(*(uint32_t*)&p0, *(uint32_t*)&p1);
        }
        return;
    }

    int pc = blockIdx.x - 512;
    int j0 = (pc & 7) * 32;
    int b = pc >> 3;
    const float* srcs[2] = { v1p + (size_t)b * DDIM * 256, v2p + (size_t)b * DDIM * 256 };
#pragma unroll
    for (int s = 0; s < 2; s++) {
        const float4* src4 = (const float4*)srcs[s];
#pragma unroll
        for (int it = 0; it < 4; it++) {
            int idx = tid + it * 256;
            int k = idx >> 3, j4 = idx & 7;
            float4 v = src4[k * 64 + (j0 >> 2) + j4];
            sb[s][j4 * 4 + 0][k] = v.x;
            sb[s][j4 * 4 + 1][k] = v.y;
            sb[s][j4 * 4 + 2][k] = v.z;
            sb[s][j4 * 4 + 3][k] = v.w;
        }
    }
    __syncthreads();
    for (int t = 0; t < 8; t++) {
        int rr = wid * 8 + t;
        int s = rr >> 5, jj = rr & 31;
        float x0 = sb[s][jj][lane * 4 + 0];
        float x1 = sb[s][jj][lane * 4 + 1];
        float x2 = sb[s][jj][lane * 4 + 2];
        float x3 = sb[s][jj][lane * 4 + 3];
        float ss = x0 * x0 + x1 * x1 + x2 * x2 + x3 * x3;
#pragma unroll
        for (int o = 16; o; o >>= 1) ss += __shfl_xor_sync(~0u, ss, o);
        float ri = 1.0f / fmaxf(sqrtf(ss), 1e-12f);
        __nv_bfloat162 p0 = __floats2bfloat162_rn(x0 * ri, x1 * ri);
        __nv_bfloat162 p1 = __floats2bfloat162_rn(x2 * ri, x3 * ri);
        size_t row = (size_t)b * 512 + s * 256 + j0 + jj;
        ((uint2*)g_P)[row * 32 + lane] = make_uint2(*(uint32_t*)&p0, *(uint32_t*)&p1);
    }
}

// epilogue micro-block: f16x2 exp, fp32 sums
#define EPI_BLOCK(MASKED)                                                       \
    {                                                                           \
        float a0 = acc[mi][ni][0] * L2E10;                                      \
        float a1 = acc[mi][ni][1] * L2E10;                                      \
        float a2 = acc[mi][ni][2] * L2E10;                                      \
        float a3 = acc[mi][ni][3] * L2E10;                                      \
        if (MASKED) {                                                           \
            int r0 = woff + mi * 16 + g, r1 = r0 + 8;                           \
            int c0 = noff + ni * 8 + t * 2, c1 = c0 + 1;                        \
            if (r0 == c0) a0 = -1e4f;                                           \
            if (r0 == c1) a1 = -1e4f;                                           \
            if (r1 == c0) a2 = -1e4f;                                           \
            if (r1 == c1) a3 = -1e4f;                                           \
        }                                                                       \
        __half2 h0 = h2ex2(__floats2half2_rn(a0, a1));                          \
        __half2 h1 = h2ex2(__floats2half2_rn(a2, a3));                          \
        float2 e01 = __half22float2(h0);                                        \
        float2 e23 = __half22float2(h1);                                        \
        rsum[mi][0] += e01.x + e01.y;                                           \
        rsum[mi][1] += e23.x + e23.y;                                           \
        csum[ni * 2 + 0] += e01.x + e23.x;                                      \
        csum[ni * 2 + 1] += e01.y + e23.y;                                      \
    }

// ---------------------------------------------------------------------------
// Main kernel: 256 threads = 2 groups x (4 warps as 2x2, 64x64 per warp).
// Group g handles tiles i = g, g+2, g+4, ... of the CTA's tile list.
// ---------------------------------------------------------------------------
__global__ void __launch_bounds__(256, 2) k_main() {
    extern __shared__ char sm[];
    uint32_t sbu = smem_u32(sm);

    int tid = threadIdx.x;
    int gid = tid >> 7, gtid = tid & 127;
    int lane = gtid & 31, wid = gtid >> 5;
    int g = lane >> 2, t = lane & 3;
    int l7 = lane & 7, l15 = lane & 15, hi = lane >> 4;
    int warpM = wid >> 1, warpN = wid & 1;
    int woff = warpM * 64, noff = warpN * 64;
    int barid = gid + 1;

    int bid = blockIdx.x;
    const char* Asrc;
    const char* Bembs;
    float* partBase;
    int pairStrideRow;
    int rowIdx;
    int bj0, bjstep, L;
    int posBj = -1;
    float* posOutA = 0;
    float* posOutB = 0;

    if (bid < NI_CTAS) {
        int x, slot, ns;
        if (bid < 512)      { x = bid >> 3;               slot = bid & 7;         ns = 8; }
        else if (bid < 640) { x = 64 + ((bid - 512) >> 2); slot = (bid - 512) & 3; ns = 4; }
        else if (bid < 672) { x = 96 + ((bid - 640) >> 1); slot = (bid - 640) & 1; ns = 2; }
        else                { x = 112 + (bid - 672);       slot = 0;               ns = 1; }
        rowIdx = x;
        bj0 = x + slot; bjstep = ns;
        L = (bj0 <= 127) ? ((127 - bj0) / ns) + 1 : 0;
        Asrc = (const char*)g_I + (size_t)x * 32768;
        Bembs = (const char*)g_I;
        partBase = g_part;
        pairStrideRow = 128;
        if (x < 64) {
            posBj = x + 64;
            posOutA = g_posI + x * 128;
            posOutB = g_posI + (x + 64) * 128;
        }
    } else {
        int pc = bid - NI_CTAS;
        int b = pc >> 2, bi = pc & 3;
        rowIdx = bi;
        bj0 = bi; bjstep = 1;
        L = 4 - bi;
        Asrc = (const char*)g_P + ((size_t)b * 512 + (size_t)bi * 128) * 256;
        Bembs = (const char*)g_P + (size_t)b * 512 * 256;
        partBase = g_pp + (size_t)b * 16 * 128;
        pairStrideRow = 4;
        if (bi < 2) {
            posBj = bi + 2;
            posOutA = g_posP + (size_t)b * 512 + bi * 128;
            posOutB = g_posP + (size_t)b * 512 + (bi + 2) * 128;
        }
    }
    if (L <= 0) return;

    uint32_t bbuf = sbu + SM_B0 + ((uint32_t)gid << 15);
    float* red = (float*)(sm + SM_RED + gid * 2048);

    // full-CTA prologue: A (all 256) + each group's first B tile
    cpa_tile256(sbu + SM_A, Asrc);
    if (gid < L) cpa_tile128(bbuf, Bembs + (size_t)(bj0 + gid * bjstep) * 32768, gtid);
    CP_COMMIT();
    CP_WAIT0();
    __syncthreads();

    uint32_t aAddr = sbu + SM_A + (uint32_t)(woff + l15) * 256;
    uint32_t bRow = bbuf + (uint32_t)(noff + l15) * 256;

    float* outRprev = 0;
    float* outCprev = 0;
    bool diagprev = false;
    bool first = true;

    for (int i = gid; i < L; i += 2) {
        int bj = bj0 + i * bjstep;
        bool diag = (bj == rowIdx);
        bool diagW = diag && (warpM == warpN);

        if (!first) {
            CP_WAIT0();                 // own group's prefetch done
            BAR_G(barid);               // B visible group-wide; red ready to flush
            float* rr = red;
            outRprev[gtid] = rr[gtid] + rr[128 + gtid];
            if (!diagprev) outCprev[gtid] = rr[256 + gtid] + rr[384 + gtid];
        }

        float acc[4][8][4];
#pragma unroll
        for (int mi = 0; mi < 4; mi++)
#pragma unroll
            for (int ni = 0; ni < 8; ni++)
#pragma unroll
                for (int q = 0; q < 4; q++) acc[mi][ni][q] = 0.f;

#pragma unroll
        for (int ks = 0; ks < 8; ks++) {
            uint32_t coff = (uint32_t)((((ks << 1) | hi) ^ l7) << 4);
            uint32_t a[4][4];
#pragma unroll
            for (int mi = 0; mi < 4; mi++)
                ldsm_x4(a[mi], aAddr + mi * 16 * 256 + coff);
            uint32_t b[4][4];
#pragma unroll
            for (int nj = 0; nj < 4; nj++)
                ldsm_x4(b[nj], bRow + nj * 16 * 256 + coff);
#pragma unroll
            for (int nj = 0; nj < 4; nj++)
#pragma unroll
                for (int mi = 0; mi < 4; mi++) {
                    mma16816(acc[mi][nj * 2 + 0], a[mi], b[nj][0], b[nj][2]);
                    mma16816(acc[mi][nj * 2 + 1], a[mi], b[nj][1], b[nj][3]);
                }
        }

        BAR_G(barid);                   // whole group done reading B
        if (i + 2 < L) {
            cpa_tile128(bbuf, Bembs + (size_t)(bj + 2 * bjstep) * 32768, gtid);
            CP_COMMIT();
        }

        // harvest positive logits: diagonal of the partner tile (raw dots)
        if (bj == posBj && warpM == warpN) {
#pragma unroll
            for (int mi = 0; mi < 4; mi++)
#pragma unroll
                for (int ni = 0; ni < 8; ni++) {
                    int r0 = woff + mi * 16 + g, r1 = r0 + 8;
                    int c0 = noff + ni * 8 + t * 2, c1 = c0 + 1;
                    if (r0 == c0) { posOutA[r0] = acc[mi][ni][0]; posOutB[r0] = acc[mi][ni][0]; }
                    if (r0 == c1) { posOutA[r0] = acc[mi][ni][1]; posOutB[r0] = acc[mi][ni][1]; }
                    if (r1 == c0) { posOutA[r1] = acc[mi][ni][2]; posOutB[r1] = acc[mi][ni][2]; }
                    if (r1 == c1) { posOutA[r1] = acc[mi][ni][3]; posOutB[r1] = acc[mi][ni][3]; }
                }
        }

        // epilogue
        float rsum[4][2];
        float csum[16];
#pragma unroll
        for (int mi = 0; mi < 4; mi++) { rsum[mi][0] = 0.f; rsum[mi][1] = 0.f; }
#pragma unroll
        for (int k2 = 0; k2 < 16; k2++) csum[k2] = 0.f;

        if (diagW) {
#pragma unroll
            for (int mi = 0; mi < 4; mi++)
#pragma unroll
                for (int ni = 0; ni < 8; ni++) EPI_BLOCK(true);
        } else {
#pragma unroll
            for (int mi = 0; mi < 4; mi++)
#pragma unroll
                for (int ni = 0; ni < 8; ni++) EPI_BLOCK(false);
        }

#pragma unroll
        for (int mi = 0; mi < 4; mi++)
#pragma unroll
            for (int h = 0; h < 2; h++) {
                float v = rsum[mi][h];
                v += __shfl_xor_sync(~0u, v, 1);
                v += __shfl_xor_sync(~0u, v, 2);
                if (t == 0) red[warpN * 128 + woff + mi * 16 + h * 8 + g] = v;
            }
#pragma unroll
        for (int k2 = 0; k2 < 16; k2++) {
            float v = csum[k2];
            v += __shfl_xor_sync(~0u, v, 4);
            v += __shfl_xor_sync(~0u, v, 8);
            v += __shfl_xor_sync(~0u, v, 16);
            if (g == 0) red[256 + warpM * 128 + noff + (k2 >> 1) * 8 + t * 2 + (k2 & 1)] = v;
        }

        outRprev = partBase + (size_t)(rowIdx * pairStrideRow + bj) * 128;
        outCprev = partBase + (size_t)(bj * pairStrideRow + rowIdx) * 128;
        diagprev = diag;
        first = false;
    }

    if (!first) {
        BAR_G(barid);
        outRprev[gtid] = red[gtid] + red[128 + gtid];
        if (!diagprev) outCprev[gtid] = red[256 + gtid] + red[384 + gtid];
    }
}

// ---------------------------------------------------------------------------
// Fused fixup + last-block combine. loss_r = log(S_r) - 10*pos_r.
// ---------------------------------------------------------------------------
__global__ void fin_all(const int* __restrict__ c1, const int* __restrict__ c2,
                        float* __restrict__ out) {
    __shared__ float S2a[8][32];
    __shared__ float S2b[256];
    __shared__ float S[128];
    __shared__ float rs[256];
    __shared__ int ri2[256];
    __shared__ int sLast;
    int tid = threadIdx.x;

    if (blockIdx.x < 512) {
        int bi = blockIdx.x >> 2, q = blockIdx.x & 3;
        int m = tid & 31, jg = tid >> 5;

        const float* base = g_part + (size_t)bi * 128 * 128 + q * 32 + m;
        float s = 0.0f;
#pragma unroll
        for (int j = jg * 16; j < jg * 16 + 16; j++) s += base[(size_t)j * 128];
        S2a[jg][m] = s;
        __syncthreads();
        if (tid < 32) {
            float v = 0.0f;
#pragma unroll
            for (int j = 0; j < 8; j++) v += S2a[j][tid];
            int r = bi * 128 + q * 32 + tid;
            float acc = logf(v) - 10.0f * g_posI[r];
#pragma unroll
            for (int o = 16; o; o >>= 1) acc += __shfl_xor_sync(~0u, acc, o);
            if (tid == 0) g_fin1[blockIdx.x] = acc;
        }
    } else {
        int pc = blockIdx.x - 512;
        int b = pc >> 2, bi = pc & 3;
        int m = tid & 127, jh = tid >> 7;

        const float* base = g_pp + ((size_t)b * 16 + bi * 4) * 128 + m;
        float s = 0.0f;
#pragma unroll
        for (int j = jh * 2; j < jh * 2 + 2; j++) s += base[(size_t)j * 128];
        S2b[tid] = s;
        __syncthreads();
        if (tid < 128) S[tid] = S2b[tid] + S2b[tid + 128];
        __syncthreads();

        float lv = 0.0f;
        int cnt = 0;
        if (tid < 128) {
            int rl = bi * 128 + tid;
            int r = b * 512 + rl;
            int c = (rl < 256) ? c1[b * 256 + rl] : c2[b * 256 + rl - 256];
            if (c != 0) {
                lv = logf(S[tid]) - 10.0f * g_posP[r];
                cnt = 1;
            }
        }
        rs[tid] = lv; ri2[tid] = cnt;
        __syncthreads();
        for (int s2 = 128; s2; s2 >>= 1) {
            if (tid < s2) { rs[tid] += rs[tid + s2]; ri2[tid] += ri2[tid + s2]; }
            __syncthreads();
        }
        if (tid == 0) { g_fin2[pc] = rs[0]; g_cnt2[pc] = ri2[0]; }
    }

    // ---- last block: final deterministic combine ----
    __threadfence();
    __syncthreads();
    if (tid == 0) {
        int ticket = atomicAdd(&g_done, 1);
        sLast = (ticket == 1535);
    }
    __syncthreads();
    if (!sLast) return;

    __shared__ float frs[256];
    __shared__ int fri[256];
    float a = g_fin1[tid] + g_fin1[tid + 256];
    float p = g_fin2[tid] + g_fin2[tid + 256] + g_fin2[tid + 512] + g_fin2[tid + 768];
    int cnt = g_cnt2[tid] + g_cnt2[tid + 256] + g_cnt2[tid + 512] + g_cnt2[tid + 768];
    frs[tid] = a; fri[tid] = cnt;
    __syncthreads();
    for (int s = 128; s; s >>= 1) {
        if (tid < s) { frs[tid] += frs[tid + s]; fri[tid] += fri[tid + s]; }
        __syncthreads();
    }
    float ins_sum = frs[0];
    int nvalid = fri[0];
    __syncthreads();
    frs[tid] = p;
    __syncthreads();
    for (int s = 128; s; s >>= 1) { if (tid < s) frs[tid] += frs[tid + s]; __syncthreads(); }
    if (tid == 0) {
        out[0] = ins_sum / (float)N_INS + frs[0] / (float)nvalid;
        g_done = 0;
    }
}

// ---------------------------------------------------------------------------
extern "C" void kernel_launch(void* const* d_in, const int* in_sizes, int n_in,
                              void* d_out, int out_size) {
    const float* v1  = (const float*)d_in[0];
    const float* v2  = (const float*)d_in[1];
    const float* v1p = (const float*)d_in[2];
    const float* v2p = (const float*)d_in[3];
    const int*   c1  = (const int*)d_in[4];
    const int*   c2  = (const int*)d_in[5];
    float* out = (float*)d_out;

    cudaFuncSetAttribute(k_main, cudaFuncAttributeMaxDynamicSharedMemorySize, SM_DYN);

    prep_all<<<2560, 256>>>(v1, v2, v1p, v2p);
    k_main<<<NI_CTAS + 1024, 256, SM_DYN>>>();
    fin_all<<<1536, 256>>>(c1, c2, out);
}

// round 17
// speedup vs baseline: 1.9966x; 1.9966x over previous
#include <cuda_runtime.h>
#include <cuda_bf16.h>
#include <cuda_fp16.h>
#include <cstdint>
#include <math.h>

// ---------------------------------------------------------------------------
// MultiLevelSimCLR: symmetric tiles, 4-warp 64x64 HMMA, occ-3 (single B buf),
// f16x2 exp epilogue, diag masking + pos harvesting, slim fixup.
// ---------------------------------------------------------------------------

#define B_INS   8192
#define N_INS   16384
#define DDIM    128
#define NPROW   131072
#define L2E10   14.4269504088896340f
#define NI_CTAS 688

// ---- static device scratch ----
__device__ __align__(16) uint32_t g_I[N_INS * 64];
__device__ __align__(16) uint32_t g_P[NPROW * 64];
__device__ float g_part[128 * 128 * 128];                // [bi][bj][m]  8.4 MB
__device__ float g_pp[256 * 16 * 128];                   // [b][i*4+j][m] 2.1 MB
__device__ float g_posI[N_INS];
__device__ float g_posP[NPROW];
__device__ float g_fin1[512];
__device__ float g_fin2[1024];
__device__ int   g_cnt2[1024];
__device__ int   g_done;

__device__ __forceinline__ __half2 h2ex2(__half2 x) {
    uint32_t xi = *(uint32_t*)&x, yi;
    asm("ex2.approx.f16x2 %0, %1;" : "=r"(yi) : "r"(xi));
    return *(__half2*)&yi;
}
__device__ __forceinline__ uint32_t smem_u32(const void* p) {
    uint32_t a;
    asm("{ .reg .u64 t; cvta.to.shared.u64 t, %1; cvt.u32.u64 %0, t; }" : "=r"(a) : "l"(p));
    return a;
}
__device__ __forceinline__ void mma16816(float* c, const uint32_t* a, uint32_t b0, uint32_t b1) {
    asm volatile(
        "mma.sync.aligned.m16n8k16.row.col.f32.bf16.bf16.f32 "
        "{%0,%1,%2,%3}, {%4,%5,%6,%7}, {%8,%9}, {%0,%1,%2,%3};"
        : "+f"(c[0]), "+f"(c[1]), "+f"(c[2]), "+f"(c[3])
        : "r"(a[0]), "r"(a[1]), "r"(a[2]), "r"(a[3]), "r"(b0), "r"(b1));
}
__device__ __forceinline__ void ldsm_x4(uint32_t* r, uint32_t addr) {
    asm volatile("ldmatrix.sync.aligned.m8n8.x4.shared.b16 {%0,%1,%2,%3}, [%4];"
        : "=r"(r[0]), "=r"(r[1]), "=r"(r[2]), "=r"(r[3]) : "r"(addr));
}
#define CP_ASYNC16(dst, src) asm volatile("cp.async.cg.shared.global [%0], [%1], 16;" :: "r"(dst), "l"(src))
#define CP_COMMIT()  asm volatile("cp.async.commit_group;" ::: "memory")
#define CP_WAIT0()   asm volatile("cp.async.wait_group 0;" ::: "memory")

// SMEM: A @0 (32KB), B @32768 (32KB), red @65536 (3KB). occ 3.
#define SM_A    0u
#define SM_B    32768u
#define SM_RED  65536
#define SM_DYN  (65536 + 3072)

__device__ __forceinline__ void cpa_tile(uint32_t dst, const char* __restrict__ src) {
    int tid = threadIdx.x;
#pragma unroll
    for (int i = 0; i < 16; i++) {
        int c = tid + i * 128;
        int r = c >> 4, cc = c & 15;
        uint32_t d = dst + r * 256 + (((uint32_t)(cc ^ (r & 7))) << 4);
        CP_ASYNC16(d, src + r * 256 + cc * 16);
    }
}

// ---------------------------------------------------------------------------
// Fused prep: blocks 0..511 instance, 512..2559 patch.
// ---------------------------------------------------------------------------
__global__ void prep_all(const float* __restrict__ v1, const float* __restrict__ v2,
                         const float* __restrict__ v1p, const float* __restrict__ v2p) {
    __shared__ float sb[2][32][129];
    int tid = threadIdx.x, lane = tid & 31, wid = tid >> 5;

    if (blockIdx.x < 512) {
        int gw = (blockIdx.x * 256 + tid) >> 5;
        for (int r = gw; r < N_INS; r += 4096) {
            const float* src = (r < B_INS) ? v1 + (size_t)r * DDIM : v2 + (size_t)(r - B_INS) * DDIM;
            float4 x = ((const float4*)src)[lane];
            float ss = x.x * x.x + x.y * x.y + x.z * x.z + x.w * x.w;
#pragma unroll
            for (int o = 16; o; o >>= 1) ss += __shfl_xor_sync(~0u, ss, o);
            float ri = 1.0f / fmaxf(sqrtf(ss), 1e-12f);
            __nv_bfloat162 p0 = __floats2bfloat162_rn(x.x * ri, x.y * ri);
            __nv_bfloat162 p1 = __floats2bfloat162_rn(x.z * ri, x.w * ri);
            ((uint2*)g_I)[(size_t)r * 32 + lane] = make_uint2(*(uint32_t*)&p0, *(uint32_t*)&p1);
        }
        return;
    }

    int pc = blockIdx.x - 512;
    int j0 = (pc & 7) * 32;
    int b = pc >> 3;
    const float* srcs[2] = { v1p + (size_t)b * DDIM * 256, v2p + (size_t)b * DDIM * 256 };
#pragma unroll
    for (int s = 0; s < 2; s++) {
        const float4* src4 = (const float4*)srcs[s];
#pragma unroll
        for (int it = 0; it < 4; it++) {
            int idx = tid + it * 256;
            int k = idx >> 3, j4 = idx & 7;
            float4 v = src4[k * 64 + (j0 >> 2) + j4];
            sb[s][j4 * 4 + 0][k] = v.x;
            sb[s][j4 * 4 + 1][k] = v.y;
            sb[s][j4 * 4 + 2][k] = v.z;
            sb[s][j4 * 4 + 3][k] = v.w;
        }
    }
    __syncthreads();
    for (int t = 0; t < 8; t++) {
        int rr = wid * 8 + t;
        int s = rr >> 5, jj = rr & 31;
        float x0 = sb[s][jj][lane * 4 + 0];
        float x1 = sb[s][jj][lane * 4 + 1];
        float x2 = sb[s][jj][lane * 4 + 2];
        float x3 = sb[s][jj][lane * 4 + 3];
        float ss = x0 * x0 + x1 * x1 + x2 * x2 + x3 * x3;
#pragma unroll
        for (int o = 16; o; o >>= 1) ss += __shfl_xor_sync(~0u, ss, o);
        float ri = 1.0f / fmaxf(sqrtf(ss), 1e-12f);
        __nv_bfloat162 p0 = __floats2bfloat162_rn(x0 * ri, x1 * ri);
        __nv_bfloat162 p1 = __floats2bfloat162_rn(x2 * ri, x3 * ri);
        size_t row = (size_t)b * 512 + s * 256 + j0 + jj;
        ((uint2*)g_P)[row * 32 + lane] = make_uint2(*(uint32_t*)&p0, *(uint32_t*)&p1);
    }
}

// epilogue micro-block: f16x2 exp, fp32 sums
#define EPI_BLOCK(MASKED)                                                       \
    {                                                                           \
        float a0 = acc[mi][ni][0] * L2E10;                                      \
        float a1 = acc[mi][ni][1] * L2E10;                                      \
        float a2 = acc[mi][ni][2] * L2E10;                                      \
        float a3 = acc[mi][ni][3] * L2E10;                                      \
        if (MASKED) {                                                           \
            int r0 = woff + mi * 16 + g, r1 = r0 + 8;                           \
            int c0 = noff + ni * 8 + t * 2, c1 = c0 + 1;                        \
            if (r0 == c0) a0 = -1e4f;                                           \
            if (r0 == c1) a1 = -1e4f;                                           \
            if (r1 == c0) a2 = -1e4f;                                           \
            if (r1 == c1) a3 = -1e4f;                                           \
        }                                                                       \
        __half2 h0 = h2ex2(__floats2half2_rn(a0, a1));                          \
        __half2 h1 = h2ex2(__floats2half2_rn(a2, a3));                          \
        float2 e01 = __half22float2(h0);                                        \
        float2 e23 = __half22float2(h1);                                        \
        rsum[mi][0] += e01.x + e01.y;                                           \
        rsum[mi][1] += e23.x + e23.y;                                           \
        csum[ni * 2 + 0] += e01.x + e23.x;                                      \
        csum[ni * 2 + 1] += e01.y + e23.y;                                      \
    }

// ---------------------------------------------------------------------------
// Main kernel: 128 threads, 4 warps as 2(M) x 2(N), 64x64 per warp, occ 3.
// Single B buffer: wait+sync -> flush -> MMA -> sync -> prefetch -> epilogue.
// ---------------------------------------------------------------------------
__global__ void __launch_bounds__(128, 3) k_main() {
    extern __shared__ char sm[];
    uint32_t sbu = smem_u32(sm);
    float* red = (float*)(sm + SM_RED);

    int tid = threadIdx.x, lane = tid & 31, wid = tid >> 5;
    int g = lane >> 2, t = lane & 3;
    int l7 = lane & 7, l15 = lane & 15, hi = lane >> 4;
    int warpM = wid >> 1, warpN = wid & 1;
    int woff = warpM * 64, noff = warpN * 64;

    int bid = blockIdx.x;
    const char* Asrc;
    const char* Bembs;
    float* partBase;
    int pairStrideRow;
    int rowIdx;
    int bj0, bjstep, L;
    int posBj = -1;
    float* posOutA = 0;
    float* posOutB = 0;

    if (bid < NI_CTAS) {
        int x, slot, ns;
        if (bid < 512)      { x = bid >> 3;               slot = bid & 7;         ns = 8; }
        else if (bid < 640) { x = 64 + ((bid - 512) >> 2); slot = (bid - 512) & 3; ns = 4; }
        else if (bid < 672) { x = 96 + ((bid - 640) >> 1); slot = (bid - 640) & 1; ns = 2; }
        else                { x = 112 + (bid - 672);       slot = 0;               ns = 1; }
        rowIdx = x;
        bj0 = x + slot; bjstep = ns;
        L = (bj0 <= 127) ? ((127 - bj0) / ns) + 1 : 0;
        Asrc = (const char*)g_I + (size_t)x * 32768;
        Bembs = (const char*)g_I;
        partBase = g_part;
        pairStrideRow = 128;
        if (x < 64) {
            posBj = x + 64;
            posOutA = g_posI + x * 128;
            posOutB = g_posI + (x + 64) * 128;
        }
    } else {
        int pc = bid - NI_CTAS;
        int b = pc >> 2, bi = pc & 3;
        rowIdx = bi;
        bj0 = bi; bjstep = 1;
        L = 4 - bi;
        Asrc = (const char*)g_P + ((size_t)b * 512 + (size_t)bi * 128) * 256;
        Bembs = (const char*)g_P + (size_t)b * 512 * 256;
        partBase = g_pp + (size_t)b * 16 * 128;
        pairStrideRow = 4;
        if (bi < 2) {
            posBj = bi + 2;
            posOutA = g_posP + (size_t)b * 512 + bi * 128;
            posOutB = g_posP + (size_t)b * 512 + (bi + 2) * 128;
        }
    }
    if (L <= 0) return;

    cpa_tile(sbu + SM_A, Asrc);
    cpa_tile(sbu + SM_B, Bembs + (size_t)bj0 * 32768);
    CP_COMMIT();

    uint32_t aAddr = sbu + SM_A + (uint32_t)(woff + l15) * 256;
    uint32_t bRow = sbu + SM_B + (uint32_t)(noff + l15) * 256;

    float* outRprev = 0;
    float* outCprev = 0;
    bool diagprev = false;

    for (int i = 0; i < L; i++) {
        int bj = bj0 + i * bjstep;
        bool diag = (bj == rowIdx);
        bool diagW = diag && (warpM == warpN);

        CP_WAIT0();
        __syncthreads();

        // flush previous tile's reduced partials
        if (i > 0) {
            outRprev[tid] = red[tid] + red[128 + tid];
            if (!diagprev) outCprev[tid] = red[256 + tid] + red[384 + tid];
        }

        float acc[4][8][4];
#pragma unroll
        for (int mi = 0; mi < 4; mi++)
#pragma unroll
            for (int ni = 0; ni < 8; ni++)
#pragma unroll
                for (int q = 0; q < 4; q++) acc[mi][ni][q] = 0.f;

#pragma unroll
        for (int ks = 0; ks < 8; ks++) {
            uint32_t coff = (uint32_t)((((ks << 1) | hi) ^ l7) << 4);
            uint32_t a[4][4];
#pragma unroll
            for (int mi = 0; mi < 4; mi++)
                ldsm_x4(a[mi], aAddr + mi * 16 * 256 + coff);
            uint32_t b[4][4];
#pragma unroll
            for (int nj = 0; nj < 4; nj++)
                ldsm_x4(b[nj], bRow + nj * 16 * 256 + coff);
#pragma unroll
            for (int nj = 0; nj < 4; nj++)
#pragma unroll
                for (int mi = 0; mi < 4; mi++) {
                    mma16816(acc[mi][nj * 2 + 0], a[mi], b[nj][0], b[nj][2]);
                    mma16816(acc[mi][nj * 2 + 1], a[mi], b[nj][1], b[nj][3]);
                }
        }

        __syncthreads();                      // B consumed by all warps
        if (i + 1 < L) {
            cpa_tile(sbu + SM_B, Bembs + (size_t)(bj + bjstep) * 32768);
            CP_COMMIT();
        }

        // harvest positive logits (diagonal of partner tile, raw dots)
        if (bj == posBj && warpM == warpN) {
#pragma unroll
            for (int mi = 0; mi < 4; mi++)
#pragma unroll
                for (int ni = 0; ni < 8; ni++) {
                    int r0 = woff + mi * 16 + g, r1 = r0 + 8;
                    int c0 = noff + ni * 8 + t * 2, c1 = c0 + 1;
                    if (r0 == c0) { posOutA[r0] = acc[mi][ni][0]; posOutB[r0] = acc[mi][ni][0]; }
                    if (r0 == c1) { posOutA[r0] = acc[mi][ni][1]; posOutB[r0] = acc[mi][ni][1]; }
                    if (r1 == c0) { posOutA[r1] = acc[mi][ni][2]; posOutB[r1] = acc[mi][ni][2]; }
                    if (r1 == c1) { posOutA[r1] = acc[mi][ni][3]; posOutB[r1] = acc[mi][ni][3]; }
                }
        }

        // epilogue: e = exp(10d) via f16x2 ex2
        float rsum[4][2];
        float csum[16];
#pragma unroll
        for (int mi = 0; mi < 4; mi++) { rsum[mi][0] = 0.f; rsum[mi][1] = 0.f; }
#pragma unroll
        for (int k2 = 0; k2 < 16; k2++) csum[k2] = 0.f;

        if (diagW) {
#pragma unroll
            for (int mi = 0; mi < 4; mi++)
#pragma unroll
                for (int ni = 0; ni < 8; ni++) EPI_BLOCK(true);
        } else {
#pragma unroll
            for (int mi = 0; mi < 4; mi++)
#pragma unroll
                for (int ni = 0; ni < 8; ni++) EPI_BLOCK(false);
        }

#pragma unroll
        for (int mi = 0; mi < 4; mi++)
#pragma unroll
            for (int h = 0; h < 2; h++) {
                float v = rsum[mi][h];
                v += __shfl_xor_sync(~0u, v, 1);
                v += __shfl_xor_sync(~0u, v, 2);
                if (t == 0) red[warpN * 128 + woff + mi * 16 + h * 8 + g] = v;
            }
#pragma unroll
        for (int k2 = 0; k2 < 16; k2++) {
            float v = csum[k2];
            v += __shfl_xor_sync(~0u, v, 4);
            v += __shfl_xor_sync(~0u, v, 8);
            v += __shfl_xor_sync(~0u, v, 16);
            if (g == 0) red[256 + warpM * 128 + noff + (k2 >> 1) * 8 + t * 2 + (k2 & 1)] = v;
        }

        outRprev = partBase + (size_t)(rowIdx * pairStrideRow + bj) * 128;
        outCprev = partBase + (size_t)(bj * pairStrideRow + rowIdx) * 128;
        diagprev = diag;
    }

    __syncthreads();
    outRprev[tid] = red[tid] + red[128 + tid];
    if (!diagprev) outCprev[tid] = red[256 + tid] + red[384 + tid];
}

// ---------------------------------------------------------------------------
// Fused fixup + last-block combine. loss_r = log(S_r) - 10*pos_r.
// ---------------------------------------------------------------------------
__global__ void fin_all(const int* __restrict__ c1, const int* __restrict__ c2,
                        float* __restrict__ out) {
    __shared__ float S2a[8][32];
    __shared__ float S2b[256];
    __shared__ float S[128];
    __shared__ float rs[256];
    __shared__ int ri2[256];
    __shared__ int sLast;
    int tid = threadIdx.x;

    if (blockIdx.x < 512) {
        int bi = blockIdx.x >> 2, q = blockIdx.x & 3;
        int m = tid & 31, jg = tid >> 5;

        const float* base = g_part + (size_t)bi * 128 * 128 + q * 32 + m;
        float s = 0.0f;
#pragma unroll
        for (int j = jg * 16; j < jg * 16 + 16; j++) s += base[(size_t)j * 128];
        S2a[jg][m] = s;
        __syncthreads();
        if (tid < 32) {
            float v = 0.0f;
#pragma unroll
            for (int j = 0; j < 8; j++) v += S2a[j][tid];
            int r = bi * 128 + q * 32 + tid;
            float acc = logf(v) - 10.0f * g_posI[r];
#pragma unroll
            for (int o = 16; o; o >>= 1) acc += __shfl_xor_sync(~0u, acc, o);
            if (tid == 0) g_fin1[blockIdx.x] = acc;
        }
    } else {
        int pc = blockIdx.x - 512;
        int b = pc >> 2, bi = pc & 3;
        int m = tid & 127, jh = tid >> 7;

        const float* base = g_pp + ((size_t)b * 16 + bi * 4) * 128 + m;
        float s = 0.0f;
#pragma unroll
        for (int j = jh * 2; j < jh * 2 + 2; j++) s += base[(size_t)j * 128];
        S2b[tid] = s;
        __syncthreads();
        if (tid < 128) S[tid] = S2b[tid] + S2b[tid + 128];
        __syncthreads();

        float lv = 0.0f;
        int cnt = 0;
        if (tid < 128) {
            int rl = bi * 128 + tid;
            int r = b * 512 + rl;
            int c = (rl < 256) ? c1[b * 256 + rl] : c2[b * 256 + rl - 256];
            if (c != 0) {
                lv = logf(S[tid]) - 10.0f * g_posP[r];
                cnt = 1;
            }
        }
        rs[tid] = lv; ri2[tid] = cnt;
        __syncthreads();
        for (int s2 = 128; s2; s2 >>= 1) {
            if (tid < s2) { rs[tid] += rs[tid + s2]; ri2[tid] += ri2[tid + s2]; }
            __syncthreads();
        }
        if (tid == 0) { g_fin2[pc] = rs[0]; g_cnt2[pc] = ri2[0]; }
    }

    // ---- last block: final deterministic combine ----
    __threadfence();
    __syncthreads();
    if (tid == 0) {
        int ticket = atomicAdd(&g_done, 1);
        sLast = (ticket == 1535);
    }
    __syncthreads();
    if (!sLast) return;

    __shared__ float frs[256];
    __shared__ int fri[256];
    float a = g_fin1[tid] + g_fin1[tid + 256];
    float p = g_fin2[tid] + g_fin2[tid + 256] + g_fin2[tid + 512] + g_fin2[tid + 768];
    int cnt = g_cnt2[tid] + g_cnt2[tid + 256] + g_cnt2[tid + 512] + g_cnt2[tid + 768];
    frs[tid] = a; fri[tid] = cnt;
    __syncthreads();
    for (int s = 128; s; s >>= 1) {
        if (tid < s) { frs[tid] += frs[tid + s]; fri[tid] += fri[tid + s]; }
        __syncthreads();
    }
    float ins_sum = frs[0];
    int nvalid = fri[0];
    __syncthreads();
    frs[tid] = p;
    __syncthreads();
    for (int s = 128; s; s >>= 1) { if (tid < s) frs[tid] += frs[tid + s]; __syncthreads(); }
    if (tid == 0) {
        out[0] = ins_sum / (float)N_INS + frs[0] / (float)nvalid;
        g_done = 0;
    }
}

// ---------------------------------------------------------------------------
extern "C" void kernel_launch(void* const* d_in, const int* in_sizes, int n_in,
                              void* d_out, int out_size) {
    const float* v1  = (const float*)d_in[0];
    const float* v2  = (const float*)d_in[1];
    const float* v1p = (const float*)d_in[2];
    const float* v2p = (const float*)d_in[3];
    const int*   c1  = (const int*)d_in[4];
    const int*   c2  = (const int*)d_in[5];
    float* out = (float*)d_out;

    cudaFuncSetAttribute(k_main, cudaFuncAttributeMaxDynamicSharedMemorySize, SM_DYN);

    prep_all<<<2560, 256>>>(v1, v2, v1p, v2p);
    k_main<<<NI_CTAS + 1024, 128, SM_DYN>>>();
    fin_all<<<1536, 256>>>(c1, c2, out);
}